// round 14
// baseline (speedup 1.0000x reference)
#include <cuda_runtime.h>
#include <stdint.h>

// out[i, 0:8] = params[idx[i]] * xs[i, 0:8]
// xs: float32 [N, 8]; idx: int32 [N]; params: float32 [V]; out: float32 [N, 8]
// N = 4194304, V = 1048576.
//
// Champion data path (43.1us best): 2 threads/row dense 16B lane-contiguous
// streams (__ldcs/__stcs evict-first), L2-only gather (__ldcg), lane-pair
// idx broadcast, UNROLL=4 front-batched chains.
// This round's single delta: PERSISTENT grid = one full wave (148 SMs x 8
// resident CTAs = 1184), grid-stride over chunks -> zero wave transitions
// instead of ~7 waves.

#define N_ROWS     4194304
#define ITEMS      (2 * N_ROWS)                 // 8M float4 half-rows
#define UNROLL     4
#define THREADS    256
#define CHUNK      (THREADS * UNROLL)           // 1024 items per CTA-iter
#define NUM_CHUNKS (ITEMS / CHUNK)              // 8192
#define BLOCKS     1184                         // 148 SMs * 8 CTAs/SM

__global__ __launch_bounds__(THREADS) void gather_mul_kernel(
    const float4* __restrict__ xs,     // [ITEMS]
    const int*    __restrict__ idx,    // [N] int32
    const float*  __restrict__ params, // [V]
    float4*       __restrict__ out)    // [ITEMS]
{
    const int tid = threadIdx.x;

    for (int c = blockIdx.x; c < NUM_CHUNKS; c += BLOCKS) {
        const int base = c * CHUNK + tid;   // item for k=0; +THREADS per k

        // 1) Batch index loads (lane pairs share an address -> broadcast).
        int j[UNROLL];
#pragma unroll
        for (int k = 0; k < UNROLL; k++)
            j[k] = __ldcs(idx + ((base + k * THREADS) >> 1));

        // 2) Batch param gathers: L2-only, table is L2-resident.
        float p[UNROLL];
#pragma unroll
        for (int k = 0; k < UNROLL; k++)
            p[k] = __ldcg(params + j[k]);

        // 3) Batch xs half-row loads: 16B lane-contiguous, evict-first.
        float4 x[UNROLL];
#pragma unroll
        for (int k = 0; k < UNROLL; k++)
            x[k] = __ldcs(xs + base + k * THREADS);

        // 4) Multiply + streaming stores (evict-first).
#pragma unroll
        for (int k = 0; k < UNROLL; k++) {
            float4 o;
            o.x = p[k] * x[k].x;
            o.y = p[k] * x[k].y;
            o.z = p[k] * x[k].z;
            o.w = p[k] * x[k].w;
            __stcs(out + base + k * THREADS, o);
        }
    }
}

extern "C" void kernel_launch(void* const* d_in, const int* in_sizes, int n_in,
                              void* d_out, int out_size)
{
    const float4* xs     = (const float4*)d_in[0];
    const int*    idx    = (const int*)d_in[1];
    const float*  params = (const float*)d_in[2];
    float4*       out    = (float4*)d_out;

    gather_mul_kernel<<<BLOCKS, THREADS>>>(xs, idx, params, out);
}

// round 15
// speedup vs baseline: 1.0583x; 1.0583x over previous
#include <cuda_runtime.h>
#include <stdint.h>

// out[i, 0:8] = params[idx[i]] * xs[i, 0:8]
// xs: float32 [N, 8]; idx: int32 [N]; params: float32 [V]; out: float32 [N, 8]
// N = 4194304, V = 1048576.
//
// FINAL kernel — best measured across 13 variants (43.1 us kernel, 5.65 TB/s,
// 71% of spec HBM, bench 47.1 us). Structure: direct LDG/STG, 2 threads per
// row so every streaming access is a dense 16B lane-contiguous wavefront;
// lane pairs broadcast the idx/param access. Streams evict-first
// (__ldcs/__stcs) keep the 4 MB param table L2-resident; gather is L2-only
// (__ldcg, no L1 reuse).
// Proven non-binding: occupancy (42-83% identical), unroll 4 vs 8, DRAM page
// layout (3 variants), L2 evict_last pinning, persistent single-wave grid.
// Proven worse: TMA/smem staging (-30..65%), write-through stores (-3..6%).
// Remaining gap to spec BW is irreducible: 16 random gather sectors/warp in
// L1tex + mixed read/write/random-sector DRAM scheduling.

#define N_ROWS  4194304
#define ITEMS   (2 * N_ROWS)                   // 8M float4 half-rows
#define UNROLL  4
#define THREADS 256
#define BLOCKS  (ITEMS / (UNROLL * THREADS))   // 8192

__global__ __launch_bounds__(THREADS) void gather_mul_kernel(
    const float4* __restrict__ xs,     // [ITEMS]
    const int*    __restrict__ idx,    // [N] int32
    const float*  __restrict__ params, // [V]
    float4*       __restrict__ out)    // [ITEMS]
{
    const int t = blockIdx.x * THREADS + threadIdx.x;
    const int S = BLOCKS * THREADS;    // 2M items per sweep

    // 1) Batch index loads (lane pairs share an address -> broadcast).
    int j[UNROLL];
#pragma unroll
    for (int k = 0; k < UNROLL; k++)
        j[k] = __ldcs(idx + ((t + k * S) >> 1));

    // 2) Batch param gathers: L2-only, table is L2-resident.
    float p[UNROLL];
#pragma unroll
    for (int k = 0; k < UNROLL; k++)
        p[k] = __ldcg(params + j[k]);

    // 3) Batch xs half-row loads: 16B lane-contiguous, evict-first.
    float4 x[UNROLL];
#pragma unroll
    for (int k = 0; k < UNROLL; k++)
        x[k] = __ldcs(xs + t + k * S);

    // 4) Multiply + streaming stores (evict-first).
#pragma unroll
    for (int k = 0; k < UNROLL; k++) {
        float4 o;
        o.x = p[k] * x[k].x;
        o.y = p[k] * x[k].y;
        o.z = p[k] * x[k].z;
        o.w = p[k] * x[k].w;
        __stcs(out + t + k * S, o);
    }
}

extern "C" void kernel_launch(void* const* d_in, const int* in_sizes, int n_in,
                              void* d_out, int out_size)
{
    const float4* xs     = (const float4*)d_in[0];
    const int*    idx    = (const int*)d_in[1];
    const float*  params = (const float*)d_in[2];
    float4*       out    = (float4*)d_out;

    gather_mul_kernel<<<BLOCKS, THREADS>>>(xs, idx, params, out);
}